// round 2
// baseline (speedup 1.0000x reference)
#include <cuda_runtime.h>
#include <cuda_bf16.h>
#include <cstdint>

// Problem constants (fixed by the reference setup)
#define N_NODES 50000
#define N_EDGES 800000
#define DIM     128
#define LN_EPS  1e-5f

// ---------------- device scratch (no allocs allowed) ----------------
__device__ float g_h[N_NODES * DIM];     // post-GEMM features
__device__ float g_buf[N_NODES * DIM];   // layer-1 output
__device__ int   g_deg[N_NODES];         // in-degree histogram
__device__ int   g_off[N_NODES + 1];     // CSR offsets (by dst)
__device__ int   g_cursor[N_NODES];      // fill cursors
__device__ int   g_srcs[N_EDGES];        // src node per sorted edge
__device__ float g_ews[N_EDGES];         // edge weight per sorted edge

// ---------------- CSR build ----------------
__global__ void zero_deg_kernel(int n) {
    int i = blockIdx.x * blockDim.x + threadIdx.x;
    if (i < n) g_deg[i] = 0;
}

__global__ void count_kernel(const int* __restrict__ eidx, int E) {
    int e = blockIdx.x * blockDim.x + threadIdx.x;
    if (e < E) {
        int d = eidx[E + e];   // dst row of edge_index
        atomicAdd(&g_deg[d], 1);
    }
}

// Single-block exclusive scan over g_deg -> g_off, g_cursor; g_off[n] = total.
__global__ void scan_kernel(int n) {
    __shared__ int wsum[32];
    int tid = threadIdx.x, lane = tid & 31, wid = tid >> 5;
    int carry = 0;
    for (int base = 0; base < n; base += 1024) {
        int i = base + tid;
        int v = (i < n) ? g_deg[i] : 0;
        int x = v;
        #pragma unroll
        for (int o = 1; o < 32; o <<= 1) {
            int y = __shfl_up_sync(0xffffffffu, x, o);
            if (lane >= o) x += y;
        }
        if (lane == 31) wsum[wid] = x;
        __syncthreads();
        if (wid == 0) {
            int s = wsum[lane];
            #pragma unroll
            for (int o = 1; o < 32; o <<= 1) {
                int y = __shfl_up_sync(0xffffffffu, s, o);
                if (lane >= o) s += y;
            }
            wsum[lane] = s;
        }
        __syncthreads();
        int incl = x + (wid > 0 ? wsum[wid - 1] : 0);
        int total = wsum[31];
        int excl = carry + incl - v;
        if (i < n) { g_off[i] = excl; g_cursor[i] = excl; }
        carry += total;
        __syncthreads();   // protect wsum before next chunk
    }
    if (tid == 0) g_off[n] = carry;
}

__global__ void fill_kernel(const int* __restrict__ eidx,
                            const float* __restrict__ ew, int E) {
    int e = blockIdx.x * blockDim.x + threadIdx.x;
    if (e < E) {
        int s = eidx[e];
        int d = eidx[E + e];
        int p = atomicAdd(&g_cursor[d], 1);
        g_srcs[p] = s;
        g_ews[p]  = ew[e];
    }
}

// ---------------- GEMM: H[n][j] = sum_k X[n][k] * W[k][j] ----------------
// One warp per row; each lane owns 4 output columns. W (64 KB) stays L1/L2-resident.
__global__ void gemm128_kernel(const float* __restrict__ X,
                               const float* __restrict__ W,
                               float* __restrict__ H, int nrows) {
    __shared__ float xs[8][DIM];
    int w = threadIdx.x >> 5, lane = threadIdx.x & 31;
    int row = blockIdx.x * 8 + w;
    if (row >= nrows) return;

    const float4* Xv = (const float4*)(X + (size_t)row * DIM);
    ((float4*)xs[w])[lane] = Xv[lane];
    __syncwarp();

    const float4* Wv = (const float4*)W;
    float4 acc = make_float4(0.f, 0.f, 0.f, 0.f);
    #pragma unroll 8
    for (int k4 = 0; k4 < 32; ++k4) {
        float4 a = ((const float4*)xs[w])[k4];
        float4 w0 = __ldg(&Wv[(4 * k4 + 0) * 32 + lane]);
        float4 w1 = __ldg(&Wv[(4 * k4 + 1) * 32 + lane]);
        float4 w2 = __ldg(&Wv[(4 * k4 + 2) * 32 + lane]);
        float4 w3 = __ldg(&Wv[(4 * k4 + 3) * 32 + lane]);
        acc.x += a.x * w0.x; acc.y += a.x * w0.y; acc.z += a.x * w0.z; acc.w += a.x * w0.w;
        acc.x += a.y * w1.x; acc.y += a.y * w1.y; acc.z += a.y * w1.z; acc.w += a.y * w1.w;
        acc.x += a.z * w2.x; acc.y += a.z * w2.y; acc.z += a.z * w2.z; acc.w += a.z * w2.w;
        acc.x += a.w * w3.x; acc.y += a.w * w3.y; acc.z += a.w * w3.z; acc.w += a.w * w3.w;
    }
    ((float4*)(H + (size_t)row * DIM))[lane] = acc;
}

// ---------------- Aggregate + bias + LayerNorm + ReLU (fused) ----------------
// One warp per destination node. Lane l owns columns 4l..4l+3.
__global__ void agg_ln_relu_kernel(const float* __restrict__ H,
                                   const float* __restrict__ bias,
                                   const float* __restrict__ gamma,
                                   const float* __restrict__ beta,
                                   float* __restrict__ out, int nrows) {
    int w = threadIdx.x >> 5, lane = threadIdx.x & 31;
    int node = blockIdx.x * 8 + w;
    if (node >= nrows) return;

    int jb = g_off[node], je = g_off[node + 1];
    const float4* Hv = (const float4*)H;

    float4 acc = make_float4(0.f, 0.f, 0.f, 0.f);
    for (int j = jb; j < je; ++j) {
        int   s   = __ldg(&g_srcs[j]);
        float wgt = __ldg(&g_ews[j]);
        float4 hv = __ldg(&Hv[(size_t)s * 32 + lane]);
        acc.x += wgt * hv.x;
        acc.y += wgt * hv.y;
        acc.z += wgt * hv.z;
        acc.w += wgt * hv.w;
    }

    float4 b4 = __ldg(&((const float4*)bias)[lane]);
    acc.x += b4.x; acc.y += b4.y; acc.z += b4.z; acc.w += b4.w;

    // warp-wide LayerNorm stats over 128 values
    float s1 = acc.x + acc.y + acc.z + acc.w;
    float s2 = acc.x * acc.x + acc.y * acc.y + acc.z * acc.z + acc.w * acc.w;
    #pragma unroll
    for (int o = 16; o > 0; o >>= 1) {
        s1 += __shfl_xor_sync(0xffffffffu, s1, o);
        s2 += __shfl_xor_sync(0xffffffffu, s2, o);
    }
    float mu  = s1 * (1.f / 128.f);
    float var = s2 * (1.f / 128.f) - mu * mu;
    float r   = rsqrtf(var + LN_EPS);

    float4 g4 = __ldg(&((const float4*)gamma)[lane]);
    float4 e4 = __ldg(&((const float4*)beta)[lane]);
    float4 y;
    y.x = fmaxf((acc.x - mu) * r * g4.x + e4.x, 0.f);
    y.y = fmaxf((acc.y - mu) * r * g4.y + e4.y, 0.f);
    y.z = fmaxf((acc.z - mu) * r * g4.z + e4.z, 0.f);
    y.w = fmaxf((acc.w - mu) * r * g4.w + e4.w, 0.f);
    ((float4*)(out + (size_t)node * DIM))[lane] = y;
}

// ---------------- launch ----------------
extern "C" void kernel_launch(void* const* d_in, const int* in_sizes, int n_in,
                              void* d_out, int out_size) {
    const float* x    = (const float*)d_in[0];
    const int*   eidx = (const int*)d_in[1];    // int32 (JAX x64 disabled)
    const float* ew   = (const float*)d_in[2];
    const float* W1   = (const float*)d_in[3];
    const float* b1   = (const float*)d_in[4];
    const float* W2   = (const float*)d_in[5];
    const float* b2   = (const float*)d_in[6];
    const float* g1   = (const float*)d_in[7];
    const float* be1  = (const float*)d_in[8];
    const float* g2   = (const float*)d_in[9];
    const float* be2  = (const float*)d_in[10];
    float* out = (float*)d_out;

    const int N = N_NODES;
    const int E = N_EDGES;

    // resolve device addresses of scratch symbols (host API, not captured)
    float *h_p, *buf_p;
    cudaGetSymbolAddress((void**)&h_p,   g_h);
    cudaGetSymbolAddress((void**)&buf_p, g_buf);

    // ---- CSR build (shared by both layers) ----
    zero_deg_kernel<<<(N + 255) / 256, 256>>>(N);
    count_kernel<<<(E + 255) / 256, 256>>>(eidx, E);
    scan_kernel<<<1, 1024>>>(N);
    fill_kernel<<<(E + 255) / 256, 256>>>(eidx, ew, E);

    const int rb = (N + 7) / 8;   // 8 warps (rows/nodes) per block of 256

    // ---- layer 1 ----
    gemm128_kernel<<<rb, 256>>>(x, W1, h_p, N);
    agg_ln_relu_kernel<<<rb, 256>>>(h_p, b1, g1, be1, buf_p, N);

    // ---- layer 2 ----
    gemm128_kernel<<<rb, 256>>>(buf_p, W2, h_p, N);
    agg_ln_relu_kernel<<<rb, 256>>>(h_p, b2, g2, be2, out, N);
}

// round 3
// speedup vs baseline: 1.5002x; 1.5002x over previous
#include <cuda_runtime.h>
#include <cuda_bf16.h>
#include <cstdint>

#define N_NODES 50000
#define N_EDGES 800000
#define DIM     128
#define LN_EPS  1e-5f

// ---------------- device scratch ----------------
__device__ float g_h[N_NODES * DIM];
__device__ float g_buf[N_NODES * DIM];
__device__ int   g_deg[N_NODES];
__device__ int   g_off[N_NODES + 1];
__device__ int   g_cursor[N_NODES];
__device__ int   g_srcs[N_EDGES];
__device__ float g_ews[N_EDGES];

// ---------------- f32x2 packed math helpers ----------------
__device__ __forceinline__ unsigned long long pack2(float a, float b) {
    unsigned long long r;
    asm("mov.b64 %0, {%1,%2};" : "=l"(r) : "f"(a), "f"(b));
    return r;
}
__device__ __forceinline__ unsigned long long fma2(unsigned long long x,
                                                   unsigned long long y,
                                                   unsigned long long z) {
    unsigned long long r;
    asm("fma.rn.f32x2 %0, %1, %2, %3;" : "=l"(r) : "l"(x), "l"(y), "l"(z));
    return r;
}
__device__ __forceinline__ float2 unpack2(unsigned long long v) {
    float2 f;
    asm("mov.b64 {%0,%1}, %2;" : "=f"(f.x), "=f"(f.y) : "l"(v));
    return f;
}

// ---------------- CSR build ----------------
__global__ void zero_deg_kernel(int n) {
    int i = blockIdx.x * blockDim.x + threadIdx.x;
    if (i < n) g_deg[i] = 0;
}

__global__ void count_kernel(const int* __restrict__ eidx, int E) {
    int e = blockIdx.x * blockDim.x + threadIdx.x;
    if (e < E) atomicAdd(&g_deg[eidx[E + e]], 1);
}

// Single-block scan, 4 elements/thread (chunk = 4096).
__global__ void scan_kernel(int n) {
    __shared__ int wsum[32];
    int tid = threadIdx.x, lane = tid & 31, wid = tid >> 5;
    int carry = 0;
    for (int base = 0; base < n; base += 4096) {
        int i0 = base + tid * 4;
        int v0 = (i0 + 0 < n) ? g_deg[i0 + 0] : 0;
        int v1 = (i0 + 1 < n) ? g_deg[i0 + 1] : 0;
        int v2 = (i0 + 2 < n) ? g_deg[i0 + 2] : 0;
        int v3 = (i0 + 3 < n) ? g_deg[i0 + 3] : 0;
        int tsum = v0 + v1 + v2 + v3;
        int x = tsum;
        #pragma unroll
        for (int o = 1; o < 32; o <<= 1) {
            int y = __shfl_up_sync(0xffffffffu, x, o);
            if (lane >= o) x += y;
        }
        if (lane == 31) wsum[wid] = x;
        __syncthreads();
        if (wid == 0) {
            int s = wsum[lane];
            #pragma unroll
            for (int o = 1; o < 32; o <<= 1) {
                int y = __shfl_up_sync(0xffffffffu, s, o);
                if (lane >= o) s += y;
            }
            wsum[lane] = s;
        }
        __syncthreads();
        int run = carry + (x - tsum) + (wid > 0 ? wsum[wid - 1] : 0);
        if (i0 + 0 < n) { g_off[i0 + 0] = run; g_cursor[i0 + 0] = run; } run += v0;
        if (i0 + 1 < n) { g_off[i0 + 1] = run; g_cursor[i0 + 1] = run; } run += v1;
        if (i0 + 2 < n) { g_off[i0 + 2] = run; g_cursor[i0 + 2] = run; } run += v2;
        if (i0 + 3 < n) { g_off[i0 + 3] = run; g_cursor[i0 + 3] = run; }
        carry += wsum[31];
        __syncthreads();
    }
    if (tid == 0) g_off[n] = carry;
}

__global__ void fill_kernel(const int* __restrict__ eidx,
                            const float* __restrict__ ew, int E) {
    int e = blockIdx.x * blockDim.x + threadIdx.x;
    if (e < E) {
        int s = eidx[e];
        int d = eidx[E + e];
        int p = atomicAdd(&g_cursor[d], 1);
        g_srcs[p] = s;
        g_ews[p]  = ew[e];
    }
}

// ---------------- GEMM: H = X @ W,  4 rows per warp, f32x2 FMA ----------------
// Block = 256 threads (8 warps) covers 32 rows. X rows staged in smem.
// Each lane owns output cols 4l..4l+3 (two f32x2 pairs per row).
__global__ __launch_bounds__(256) void gemm128_kernel(
        const float* __restrict__ X, const float* __restrict__ W,
        float* __restrict__ H, int nrows) {
    __shared__ float xs[32][DIM];   // 16 KB
    int tid = threadIdx.x, lane = tid & 31, w = tid >> 5;
    int blockRow = blockIdx.x * 32;

    // stage 32 rows: each pass loads 8 rows (8 warps x 1 row, float4 per lane)
    #pragma unroll
    for (int r = 0; r < 32; r += 8) {
        int row = blockRow + r + w;
        if (row < nrows)
            ((float4*)xs[r + w])[lane] = ((const float4*)(X + (size_t)row * DIM))[lane];
    }
    __syncthreads();

    int myRow0 = blockRow + w * 4;   // this warp's 4 rows
    const ulonglong2* Wv = (const ulonglong2*)W;   // each = 4 floats (2 f32x2 pairs)

    unsigned long long a01[4], a23[4];
    #pragma unroll
    for (int r = 0; r < 4; ++r) { a01[r] = pack2(0.f, 0.f); a23[r] = a01[r]; }

    #pragma unroll 4
    for (int k4 = 0; k4 < 32; ++k4) {
        // W rows 4k4..4k4+3, cols 4l..4l+3
        ulonglong2 w0 = __ldg(&Wv[(4 * k4 + 0) * 32 + lane]);
        ulonglong2 w1 = __ldg(&Wv[(4 * k4 + 1) * 32 + lane]);
        ulonglong2 w2 = __ldg(&Wv[(4 * k4 + 2) * 32 + lane]);
        ulonglong2 w3 = __ldg(&Wv[(4 * k4 + 3) * 32 + lane]);
        #pragma unroll
        for (int r = 0; r < 4; ++r) {
            float4 a = ((const float4*)xs[w * 4 + r])[k4];
            unsigned long long ax = pack2(a.x, a.x);
            unsigned long long ay = pack2(a.y, a.y);
            unsigned long long az = pack2(a.z, a.z);
            unsigned long long aw = pack2(a.w, a.w);
            a01[r] = fma2(w0.x, ax, a01[r]);  a23[r] = fma2(w0.y, ax, a23[r]);
            a01[r] = fma2(w1.x, ay, a01[r]);  a23[r] = fma2(w1.y, ay, a23[r]);
            a01[r] = fma2(w2.x, az, a01[r]);  a23[r] = fma2(w2.y, az, a23[r]);
            a01[r] = fma2(w3.x, aw, a01[r]);  a23[r] = fma2(w3.y, aw, a23[r]);
        }
    }

    #pragma unroll
    for (int r = 0; r < 4; ++r) {
        int row = myRow0 + r;
        if (row < nrows) {
            float2 lo = unpack2(a01[r]), hi = unpack2(a23[r]);
            float4 o = make_float4(lo.x, lo.y, hi.x, hi.y);
            ((float4*)(H + (size_t)row * DIM))[lane] = o;
        }
    }
}

// ---------------- Aggregate + bias + LayerNorm + ReLU (fused) ----------------
__global__ __launch_bounds__(256) void agg_ln_relu_kernel(
        const float* __restrict__ H,
        const float* __restrict__ bias,
        const float* __restrict__ gamma,
        const float* __restrict__ beta,
        float* __restrict__ out, int nrows) {
    int w = threadIdx.x >> 5, lane = threadIdx.x & 31;
    int node = blockIdx.x * 8 + w;
    if (node >= nrows) return;

    int jb = g_off[node], je = g_off[node + 1];
    const float4* Hv = (const float4*)H;

    float4 acc = make_float4(0.f, 0.f, 0.f, 0.f);
    int j = jb;
    for (; j + 4 <= je; j += 4) {
        int   s0 = __ldg(&g_srcs[j + 0]);
        int   s1 = __ldg(&g_srcs[j + 1]);
        int   s2 = __ldg(&g_srcs[j + 2]);
        int   s3 = __ldg(&g_srcs[j + 3]);
        float e0 = __ldg(&g_ews[j + 0]);
        float e1 = __ldg(&g_ews[j + 1]);
        float e2 = __ldg(&g_ews[j + 2]);
        float e3 = __ldg(&g_ews[j + 3]);
        float4 h0 = __ldg(&Hv[(size_t)s0 * 32 + lane]);
        float4 h1 = __ldg(&Hv[(size_t)s1 * 32 + lane]);
        float4 h2 = __ldg(&Hv[(size_t)s2 * 32 + lane]);
        float4 h3 = __ldg(&Hv[(size_t)s3 * 32 + lane]);
        acc.x += e0 * h0.x; acc.y += e0 * h0.y; acc.z += e0 * h0.z; acc.w += e0 * h0.w;
        acc.x += e1 * h1.x; acc.y += e1 * h1.y; acc.z += e1 * h1.z; acc.w += e1 * h1.w;
        acc.x += e2 * h2.x; acc.y += e2 * h2.y; acc.z += e2 * h2.z; acc.w += e2 * h2.w;
        acc.x += e3 * h3.x; acc.y += e3 * h3.y; acc.z += e3 * h3.z; acc.w += e3 * h3.w;
    }
    for (; j < je; ++j) {
        int   s   = __ldg(&g_srcs[j]);
        float wgt = __ldg(&g_ews[j]);
        float4 hv = __ldg(&Hv[(size_t)s * 32 + lane]);
        acc.x += wgt * hv.x; acc.y += wgt * hv.y;
        acc.z += wgt * hv.z; acc.w += wgt * hv.w;
    }

    float4 b4 = __ldg(&((const float4*)bias)[lane]);
    acc.x += b4.x; acc.y += b4.y; acc.z += b4.z; acc.w += b4.w;

    float s1 = acc.x + acc.y + acc.z + acc.w;
    float s2 = acc.x * acc.x + acc.y * acc.y + acc.z * acc.z + acc.w * acc.w;
    #pragma unroll
    for (int o = 16; o > 0; o >>= 1) {
        s1 += __shfl_xor_sync(0xffffffffu, s1, o);
        s2 += __shfl_xor_sync(0xffffffffu, s2, o);
    }
    float mu  = s1 * (1.f / 128.f);
    float var = s2 * (1.f / 128.f) - mu * mu;
    float r   = rsqrtf(var + LN_EPS);

    float4 g4 = __ldg(&((const float4*)gamma)[lane]);
    float4 e4 = __ldg(&((const float4*)beta)[lane]);
    float4 y;
    y.x = fmaxf((acc.x - mu) * r * g4.x + e4.x, 0.f);
    y.y = fmaxf((acc.y - mu) * r * g4.y + e4.y, 0.f);
    y.z = fmaxf((acc.z - mu) * r * g4.z + e4.z, 0.f);
    y.w = fmaxf((acc.w - mu) * r * g4.w + e4.w, 0.f);
    ((float4*)(out + (size_t)node * DIM))[lane] = y;
}

// ---------------- launch ----------------
extern "C" void kernel_launch(void* const* d_in, const int* in_sizes, int n_in,
                              void* d_out, int out_size) {
    const float* x    = (const float*)d_in[0];
    const int*   eidx = (const int*)d_in[1];
    const float* ew   = (const float*)d_in[2];
    const float* W1   = (const float*)d_in[3];
    const float* b1   = (const float*)d_in[4];
    const float* W2   = (const float*)d_in[5];
    const float* b2   = (const float*)d_in[6];
    const float* g1   = (const float*)d_in[7];
    const float* be1  = (const float*)d_in[8];
    const float* g2   = (const float*)d_in[9];
    const float* be2  = (const float*)d_in[10];
    float* out = (float*)d_out;

    const int N = N_NODES;
    const int E = N_EDGES;

    float *h_p, *buf_p;
    cudaGetSymbolAddress((void**)&h_p,   g_h);
    cudaGetSymbolAddress((void**)&buf_p, g_buf);

    zero_deg_kernel<<<(N + 255) / 256, 256>>>(N);
    count_kernel<<<(E + 255) / 256, 256>>>(eidx, E);
    scan_kernel<<<1, 1024>>>(N);
    fill_kernel<<<(E + 255) / 256, 256>>>(eidx, ew, E);

    const int gemm_blocks = (N + 31) / 32;
    const int agg_blocks  = (N + 7) / 8;

    gemm128_kernel<<<gemm_blocks, 256>>>(x, W1, h_p, N);
    agg_ln_relu_kernel<<<agg_blocks, 256>>>(h_p, b1, g1, be1, buf_p, N);

    gemm128_kernel<<<gemm_blocks, 256>>>(buf_p, W2, h_p, N);
    agg_ln_relu_kernel<<<agg_blocks, 256>>>(h_p, b2, g2, be2, out, N);
}